// round 15
// baseline (speedup 1.0000x reference)
#include <cuda_runtime.h>
#include <cuda_fp16.h>
#include <cstdint>
#include <math.h>

// Problem constants
#define BATCH 1024
#define FDIM  128
#define EDIM  256
#define HEADS 8
#define DHEAD 32
#define MROWS (BATCH * FDIM)   // 131072
#define NCOLS (4 * EDIM)       // 1024 : [Q | K | V | R]

// ---------------------------------------------------------------------------
// Device scratch (no allocations allowed)
// g_att: per (row, head) packed fp16 record: [Qhi(32) | Qlo(32) | Khi(32) | Vhi(32)]
// ---------------------------------------------------------------------------
__device__ __half g_att[(size_t)MROWS * HEADS * 128];    // 268 MB
__device__ float  g_R[(size_t)MROWS * EDIM];             // 134 MB residual fp32
__device__ __half g_Ahi[(size_t)MROWS * EDIM];           // input hi
__device__ __half g_Alo[(size_t)MROWS * EDIM];           // input lo
__device__ __half g_Bh[(size_t)NCOLS * EDIM];            // [n][k] = W[k][n], fp16

// ---------------------------------------------------------------------------
// mma.sync m16n8k16 fp16 -> f32 ; ldmatrix fragment loads
// ---------------------------------------------------------------------------
__device__ __forceinline__ void mma16816(float* c, const uint32_t* a, const uint32_t* b) {
    asm volatile(
        "mma.sync.aligned.m16n8k16.row.col.f32.f16.f16.f32 "
        "{%0,%1,%2,%3}, {%4,%5,%6,%7}, {%8,%9}, {%0,%1,%2,%3};"
        : "+f"(c[0]), "+f"(c[1]), "+f"(c[2]), "+f"(c[3])
        : "r"(a[0]), "r"(a[1]), "r"(a[2]), "r"(a[3]), "r"(b[0]), "r"(b[1]));
}

__device__ __forceinline__ void ldsm_x4(uint32_t* r, uint32_t saddr) {
    asm volatile("ldmatrix.sync.aligned.m8n8.x4.shared.b16 {%0,%1,%2,%3}, [%4];"
                 : "=r"(r[0]), "=r"(r[1]), "=r"(r[2]), "=r"(r[3]) : "r"(saddr));
}

__device__ __forceinline__ void ldsm_x4_trans(uint32_t* r, uint32_t saddr) {
    asm volatile("ldmatrix.sync.aligned.m8n8.x4.trans.shared.b16 {%0,%1,%2,%3}, [%4];"
                 : "=r"(r[0]), "=r"(r[1]), "=r"(r[2]), "=r"(r[3]) : "r"(saddr));
}

__device__ __forceinline__ void split_half(float x, __half& h, __half& l) {
    h = __float2half_rn(x);
    l = __float2half_rn(x - __half2float(h));
}

__device__ __forceinline__ uint32_t pack2h(__half a, __half b) {
    __half2 t(a, b);
    return *(uint32_t*)&t;
}

__device__ __forceinline__ uint32_t smem_u32(const void* p) {
    uint32_t a;
    asm("{ .reg .u64 t; cvta.to.shared.u64 t, %1; cvt.u32.u64 %0, t; }" : "=r"(a) : "l"(p));
    return a;
}

__device__ __forceinline__ void cp16(uint32_t saddr, const void* gptr) {
    asm volatile("cp.async.cg.shared.global [%0], [%1], 16;" :: "r"(saddr), "l"(gptr));
}
#define CP_COMMIT() asm volatile("cp.async.commit_group;" ::: "memory")
#define CP_WAIT(N)  asm volatile("cp.async.wait_group %0;" :: "n"(N) : "memory")

// ---------------------------------------------------------------------------
// Conversion kernels
// ---------------------------------------------------------------------------
__global__ __launch_bounds__(256) void convert_A_kernel(const float* __restrict__ A) {
    size_t i = ((size_t)blockIdx.x * blockDim.x + threadIdx.x) * 4;
    if (i >= (size_t)MROWS * EDIM) return;
    float4 v = *(const float4*)&A[i];
    __half h0, l0, h1, l1, h2, l2, h3, l3;
    split_half(v.x, h0, l0); split_half(v.y, h1, l1);
    split_half(v.z, h2, l2); split_half(v.w, h3, l3);
    __half2* ph = (__half2*)&g_Ahi[i];
    __half2* pl = (__half2*)&g_Alo[i];
    ph[0] = __half2(h0, h1); ph[1] = __half2(h2, h3);
    pl[0] = __half2(l0, l1); pl[1] = __half2(l2, l3);
}

__global__ __launch_bounds__(256) void convert_W_kernel(
    const float* __restrict__ Wq, const float* __restrict__ Wk,
    const float* __restrict__ Wv, const float* __restrict__ Wr) {
    int id = blockIdx.x * blockDim.x + threadIdx.x;   // n*256 + k
    if (id >= NCOLS * EDIM) return;
    int n = id >> 8;
    int k = id & 255;
    const float* W = (n < 256) ? Wq : (n < 512) ? Wk : (n < 768) ? Wv : Wr;
    g_Bh[(size_t)n * EDIM + k] = __float2half_rn(W[(size_t)k * EDIM + (n & 255)]);
}

// ---------------------------------------------------------------------------
// Projection GEMM via mma.sync + ldmatrix, cp.async 2-stage.
// Q,K (blockIdx.x < 4): split-fp16 2 products; V,R: single product.
// Epilogue routes into the packed g_att record (Q: hi/lo, K: hi, V: hi) or g_R.
// ---------------------------------------------------------------------------
#define PSTR 72
#define PROJ_TILE (128 * PSTR * 2)           // 18432 B
#define PROJ_STAGE (3 * PROJ_TILE)           // 55296 B
#define PROJ_SMEM_BYTES (2 * PROJ_STAGE)     // 110592 B

__global__ __launch_bounds__(256, 2) void proj_mma_kernel() {
    extern __shared__ __half smh[];
    const uint32_t sbase = smem_u32(smh);

    const int tid = threadIdx.x;
    const int wid = tid >> 5;
    const int lane = tid & 31;
    const int m0 = blockIdx.y * 128;
    const int n0 = blockIdx.x * 128;
    const bool twoProd = (blockIdx.x < 4);   // Q,K regions
    const int wm = (wid & 1) * 64;
    const int wn = (wid >> 1) * 32;
    const int grp = lane >> 2;
    const int tig = lane & 3;

    const int a_row = lane & 15;
    const int a_col = (lane >> 4) * 8;
    const int b_row = lane & 7;
    const int b_col = ((lane >> 3) & 1) * 8;
    const int b_nf  = lane >> 4;

    float acc[4][4][4];
#pragma unroll
    for (int mf = 0; mf < 4; mf++)
#pragma unroll
        for (int nf = 0; nf < 4; nf++)
#pragma unroll
            for (int r = 0; r < 4; r++) acc[mf][nf][r] = 0.f;

    auto fill = [&](int c, int st) {
        const int k0 = c * 64;
        const uint32_t sa = sbase + st * PROJ_STAGE;
#pragma unroll
        for (int it = 0; it < 4; it++) {
            int idx = tid + it * 256;          // 0..1023
            int r = idx >> 3;
            int c16 = idx & 7;
            uint32_t off = (uint32_t)(r * PSTR + c16 * 8) * 2;
            size_t ga = (size_t)(m0 + r) * EDIM + k0 + c16 * 8;
            size_t gb = (size_t)(n0 + r) * EDIM + k0 + c16 * 8;
            cp16(sa + off, g_Ahi + ga);
            if (twoProd) cp16(sa + PROJ_TILE + off, g_Alo + ga);
            cp16(sa + 2 * PROJ_TILE + off, g_Bh + gb);
        }
    };

    fill(0, 0); CP_COMMIT();
    fill(1, 1); CP_COMMIT();

    for (int c = 0; c < 4; c++) {
        if (c < 3) { CP_WAIT(1); } else { CP_WAIT(0); }
        __syncthreads();

        const int st = c & 1;
        const uint32_t sAh = sbase + st * PROJ_STAGE;
        const uint32_t sAl = sAh + PROJ_TILE;
        const uint32_t sB  = sAh + 2 * PROJ_TILE;

#pragma unroll
        for (int kk = 0; kk < 4; kk++) {
            const int kb0 = kk * 16;
            uint32_t b01[4], b23[4];
            ldsm_x4(b01, sB + (uint32_t)(((wn + b_nf * 8 + b_row) * PSTR) + kb0 + b_col) * 2);
            ldsm_x4(b23, sB + (uint32_t)(((wn + (2 + b_nf) * 8 + b_row) * PSTR) + kb0 + b_col) * 2);
#pragma unroll
            for (int mf = 0; mf < 4; mf++) {
                const uint32_t aoff = (uint32_t)(((wm + mf * 16 + a_row) * PSTR) + kb0 + a_col) * 2;
                uint32_t ah[4], al[4];
                ldsm_x4(ah, sAh + aoff);
                if (twoProd) ldsm_x4(al, sAl + aoff);
#pragma unroll
                for (int nf = 0; nf < 4; nf++) {
                    const uint32_t* bp = (nf < 2) ? (b01 + (nf & 1) * 2) : (b23 + (nf & 1) * 2);
                    mma16816(acc[mf][nf], ah, bp);
                    if (twoProd) mma16816(acc[mf][nf], al, bp);
                }
            }
        }
        __syncthreads();
        if (c + 2 < 4) { fill(c + 2, st); CP_COMMIT(); }
    }

    // Epilogue: region 0=Q (hi/lo), 1=K (hi), 2=V (hi) into g_att; 3=R fp32.
    const int region = blockIdx.x >> 1;
    const int nbase = (blockIdx.x & 1) * 128;

#pragma unroll
    for (int mf = 0; mf < 4; mf++) {
        size_t m = (size_t)(m0 + wm + mf * 16 + grp);
#pragma unroll
        for (int nf = 0; nf < 4; nf++) {
            int n = nbase + wn + nf * 8 + tig * 2;   // 0..255 within region
            float a0 = acc[mf][nf][0], a1 = acc[mf][nf][1];
            float a2 = acc[mf][nf][2], a3 = acc[mf][nf][3];
            if (region == 3) {
                *(float2*)&g_R[m * EDIM + n] = make_float2(a0, a1);
                *(float2*)&g_R[(m + 8) * EDIM + n] = make_float2(a2, a3);
            } else {
                const int head = n >> 5;
                const int d = n & 31;
                size_t r0 = (m * HEADS + head) * 128;
                size_t r1 = ((m + 8) * HEADS + head) * 128;
                if (region == 0) {
                    __half h0, l0, h1, l1, h2, l2, h3, l3;
                    split_half(a0, h0, l0); split_half(a1, h1, l1);
                    split_half(a2, h2, l2); split_half(a3, h3, l3);
                    *(__half2*)&g_att[r0 + d]      = __half2(h0, h1);
                    *(__half2*)&g_att[r0 + 32 + d] = __half2(l0, l1);
                    *(__half2*)&g_att[r1 + d]      = __half2(h2, h3);
                    *(__half2*)&g_att[r1 + 32 + d] = __half2(l2, l3);
                } else {
                    const int seg = (region == 1) ? 64 : 96;
                    *(__half2*)&g_att[r0 + seg + d] = __floats2half2_rn(a0, a1);
                    *(__half2*)&g_att[r1 + seg + d] = __floats2half2_rn(a2, a3);
                }
            }
        }
    }
}

// ---------------------------------------------------------------------------
// Attention: packed fp16 records, cp.async loads, ldmatrix (+trans for V).
// smem: 128 rows x 136 halves (record 128 + pad 8) = 34816 B.
// ---------------------------------------------------------------------------
#define ASTR 136
#define ATT_SMEM_BYTES (128 * ASTR * 2)      // 34816

__global__ __launch_bounds__(256, 2) void attn_mma_kernel(float* __restrict__ out)
{
    extern __shared__ __half satt[];
    const uint32_t sb = smem_u32(satt);

    const int bh = blockIdx.x;
    const int b = bh >> 3;
    const int h = bh & 7;
    const int tid = threadIdx.x;
    const int wid = tid >> 5;
    const int lane = tid & 31;
    const int grp = lane >> 2;
    const int tig = lane & 3;

    const int a_row = lane & 15;
    const int a_col = (lane >> 4) * 8;
    const int b_row = lane & 7;
    const int b_col = ((lane >> 3) & 1) * 8;
    const int b_nf  = lane >> 4;
    // trans-ldmatrix lane addressing (for V)
    const int t_k  = (lane & 7) + ((lane >> 3) & 1) * 8;   // k-row within 16
    const int t_n8 = (lane >> 4) * 8;                      // n-block

    // ---- async load of packed records: row r of head h ----
    const size_t gbase = ((size_t)(b * FDIM) * HEADS + h) * 128;
#pragma unroll
    for (int s = 0; s < 8; s++) {
        int idx = tid + s * 256;               // 0..2047
        int r = idx >> 4;                      // 0..127
        int c16 = idx & 15;                    // 16B chunk within record
        cp16(sb + (uint32_t)(r * ASTR + c16 * 8) * 2,
             g_att + gbase + (size_t)r * (HEADS * 128) + c16 * 8);
    }
    CP_COMMIT();
    CP_WAIT(0);
    __syncthreads();

    // ---- S = Q K^T : warp wid handles rows wm..wm+15, all 128 cols ----
    const int wm = wid * 16;
    float acc[16][4];
#pragma unroll
    for (int nf = 0; nf < 16; nf++)
#pragma unroll
        for (int r = 0; r < 4; r++) acc[nf][r] = 0.f;

#pragma unroll
    for (int kk = 0; kk < 2; kk++) {
        const int kb0 = kk * 16;
        const uint32_t aoff = (uint32_t)(((wm + a_row) * ASTR) + kb0 + a_col) * 2;
        uint32_t ah[4], al[4];
        ldsm_x4(ah, sb + aoff);                 // Qhi at seg 0
        ldsm_x4(al, sb + aoff + 64);            // Qlo at seg 32 (+64 B)
#pragma unroll
        for (int j = 0; j < 8; j++) {           // nf pairs (2j, 2j+1)
            uint32_t bf[4];
            ldsm_x4(bf, sb + (uint32_t)((((2 * j + b_nf) * 8 + b_row) * ASTR) + 64 + kb0 + b_col) * 2);
            mma16816(acc[2 * j],     ah, bf);
            mma16816(acc[2 * j],     al, bf);
            mma16816(acc[2 * j + 1], ah, bf + 2);
            mma16816(acc[2 * j + 1], al, bf + 2);
        }
    }

    // ---- softmax in registers ----
    float mx0 = -1e30f, mx1 = -1e30f;
#pragma unroll
    for (int nf = 0; nf < 16; nf++) {
        mx0 = fmaxf(mx0, fmaxf(acc[nf][0], acc[nf][1]));
        mx1 = fmaxf(mx1, fmaxf(acc[nf][2], acc[nf][3]));
    }
#pragma unroll
    for (int o = 2; o >= 1; o >>= 1) {
        mx0 = fmaxf(mx0, __shfl_xor_sync(0xffffffffu, mx0, o));
        mx1 = fmaxf(mx1, __shfl_xor_sync(0xffffffffu, mx1, o));
    }
    float s0 = 0.f, s1 = 0.f;
#pragma unroll
    for (int nf = 0; nf < 16; nf++) {
        acc[nf][0] = __expf(acc[nf][0] - mx0);
        acc[nf][1] = __expf(acc[nf][1] - mx0);
        acc[nf][2] = __expf(acc[nf][2] - mx1);
        acc[nf][3] = __expf(acc[nf][3] - mx1);
        s0 += acc[nf][0] + acc[nf][1];
        s1 += acc[nf][2] + acc[nf][3];
    }
#pragma unroll
    for (int o = 2; o >= 1; o >>= 1) {
        s0 += __shfl_xor_sync(0xffffffffu, s0, o);
        s1 += __shfl_xor_sync(0xffffffffu, s1, o);
    }
    const float inv0 = 1.0f / s0;
    const float inv1 = 1.0f / s1;

    // ---- pack P into A-fragments (hi/lo), consuming acc ----
    uint32_t ph[8][4], pl[8][4];
#pragma unroll
    for (int j = 0; j < 8; j++) {
        float p00 = acc[2 * j][0] * inv0,     p01 = acc[2 * j][1] * inv0;
        float p02 = acc[2 * j][2] * inv1,     p03 = acc[2 * j][3] * inv1;
        float p10 = acc[2 * j + 1][0] * inv0, p11 = acc[2 * j + 1][1] * inv0;
        float p12 = acc[2 * j + 1][2] * inv1, p13 = acc[2 * j + 1][3] * inv1;
        __half ha, la, hb, lb;
        split_half(p00, ha, la); split_half(p01, hb, lb);
        ph[j][0] = pack2h(ha, hb); pl[j][0] = pack2h(la, lb);
        split_half(p02, ha, la); split_half(p03, hb, lb);
        ph[j][1] = pack2h(ha, hb); pl[j][1] = pack2h(la, lb);
        split_half(p10, ha, la); split_half(p11, hb, lb);
        ph[j][2] = pack2h(ha, hb); pl[j][2] = pack2h(la, lb);
        split_half(p12, ha, la); split_half(p13, hb, lb);
        ph[j][3] = pack2h(ha, hb); pl[j][3] = pack2h(la, lb);
    }

    // ---- O = P V : V row-major in record (seg 96), B-frags via ldmatrix.trans ----
    float o[4][4];
#pragma unroll
    for (int nf = 0; nf < 4; nf++)
#pragma unroll
        for (int r = 0; r < 4; r++) o[nf][r] = 0.f;

#pragma unroll
    for (int kk = 0; kk < 8; kk++) {
        const int kb0 = kk * 16;
        // x4 trans: matrices (k,k+8) x (n0, n0+8); two calls cover n=0..31
        uint32_t b01[4], b23[4];
        ldsm_x4_trans(b01, sb + (uint32_t)(((kb0 + t_k) * ASTR) + 96 + 0  + t_n8) * 2);
        ldsm_x4_trans(b23, sb + (uint32_t)(((kb0 + t_k) * ASTR) + 96 + 16 + t_n8) * 2);
#pragma unroll
        for (int nf = 0; nf < 4; nf++) {
            const uint32_t* bp = (nf < 2) ? (b01 + (nf & 1) * 2) : (b23 + (nf & 1) * 2);
            mma16816(o[nf], ph[kk], bp);
            mma16816(o[nf], pl[kk], bp);
        }
    }

    // ---- epilogue: + residual, ReLU, store ----
    const size_t orowbase = (size_t)(b * FDIM);
    const int colQ = h * DHEAD;
#pragma unroll
    for (int nf = 0; nf < 4; nf++) {
        int cc = nf * 8 + tig * 2;
        int r0 = wm + grp;
        int r1 = r0 + 8;
        float2 rr0 = *(const float2*)&g_R[(orowbase + r0) * EDIM + colQ + cc];
        float2 rr1 = *(const float2*)&g_R[(orowbase + r1) * EDIM + colQ + cc];
        float2 o0, o1;
        o0.x = fmaxf(o[nf][0] + rr0.x, 0.f);
        o0.y = fmaxf(o[nf][1] + rr0.y, 0.f);
        o1.x = fmaxf(o[nf][2] + rr1.x, 0.f);
        o1.y = fmaxf(o[nf][3] + rr1.y, 0.f);
        *(float2*)&out[(orowbase + r0) * EDIM + colQ + cc] = o0;
        *(float2*)&out[(orowbase + r1) * EDIM + colQ + cc] = o1;
    }
}

// ---------------------------------------------------------------------------
// Launch
// ---------------------------------------------------------------------------
extern "C" void kernel_launch(void* const* d_in, const int* in_sizes, int n_in,
                              void* d_out, int out_size)
{
    const float* inputs = (const float*)d_in[0];
    const float* Wq     = (const float*)d_in[1];
    const float* Wk     = (const float*)d_in[2];
    const float* Wv     = (const float*)d_in[3];
    const float* Wr     = (const float*)d_in[4];
    float* out = (float*)d_out;

    cudaFuncSetAttribute(proj_mma_kernel, cudaFuncAttributeMaxDynamicSharedMemorySize,
                         PROJ_SMEM_BYTES);
    cudaFuncSetAttribute(attn_mma_kernel, cudaFuncAttributeMaxDynamicSharedMemorySize,
                         ATT_SMEM_BYTES);

    convert_A_kernel<<<(MROWS * EDIM / 4 + 255) / 256, 256>>>(inputs);
    convert_W_kernel<<<(NCOLS * EDIM + 255) / 256, 256>>>(Wq, Wk, Wv, Wr);

    dim3 gridP(NCOLS / 128, MROWS / 128);   // 8 x 1024
    proj_mma_kernel<<<gridP, 256, PROJ_SMEM_BYTES>>>();

    attn_mma_kernel<<<BATCH * HEADS, 256, ATT_SMEM_BYTES>>>(out);
}

// round 16
// speedup vs baseline: 1.0451x; 1.0451x over previous
#include <cuda_runtime.h>
#include <cuda_fp16.h>
#include <cstdint>
#include <math.h>

// Problem constants
#define BATCH 1024
#define FDIM  128
#define EDIM  256
#define HEADS 8
#define DHEAD 32
#define MROWS (BATCH * FDIM)   // 131072
#define NCOLS (4 * EDIM)       // 1024 : [Q | K | V | R]

// ---------------------------------------------------------------------------
// Device scratch (no allocations allowed)
// g_att: per (row, head) packed fp16 record: [Qhi(32) | Qlo(32) | Khi(32) | Vhi(32)]
// ---------------------------------------------------------------------------
__device__ __half g_att[(size_t)MROWS * HEADS * 128];    // 268 MB
__device__ float  g_R[(size_t)MROWS * EDIM];             // 134 MB residual fp32
__device__ __half g_Ahi[(size_t)MROWS * EDIM];           // input hi
__device__ __half g_Alo[(size_t)MROWS * EDIM];           // input lo
__device__ __half g_Bh[(size_t)NCOLS * EDIM];            // [n][k] = W[k][n], fp16

// ---------------------------------------------------------------------------
// mma.sync m16n8k16 fp16 -> f32 ; ldmatrix fragment loads
// ---------------------------------------------------------------------------
__device__ __forceinline__ void mma16816(float* c, const uint32_t* a, const uint32_t* b) {
    asm volatile(
        "mma.sync.aligned.m16n8k16.row.col.f32.f16.f16.f32 "
        "{%0,%1,%2,%3}, {%4,%5,%6,%7}, {%8,%9}, {%0,%1,%2,%3};"
        : "+f"(c[0]), "+f"(c[1]), "+f"(c[2]), "+f"(c[3])
        : "r"(a[0]), "r"(a[1]), "r"(a[2]), "r"(a[3]), "r"(b[0]), "r"(b[1]));
}

__device__ __forceinline__ void ldsm_x4(uint32_t* r, uint32_t saddr) {
    asm volatile("ldmatrix.sync.aligned.m8n8.x4.shared.b16 {%0,%1,%2,%3}, [%4];"
                 : "=r"(r[0]), "=r"(r[1]), "=r"(r[2]), "=r"(r[3]) : "r"(saddr));
}

__device__ __forceinline__ void ldsm_x4_trans(uint32_t* r, uint32_t saddr) {
    asm volatile("ldmatrix.sync.aligned.m8n8.x4.trans.shared.b16 {%0,%1,%2,%3}, [%4];"
                 : "=r"(r[0]), "=r"(r[1]), "=r"(r[2]), "=r"(r[3]) : "r"(saddr));
}

__device__ __forceinline__ void split_half(float x, __half& h, __half& l) {
    h = __float2half_rn(x);
    l = __float2half_rn(x - __half2float(h));
}

__device__ __forceinline__ uint32_t pack2h(__half a, __half b) {
    __half2 t(a, b);
    return *(uint32_t*)&t;
}

__device__ __forceinline__ uint32_t smem_u32(const void* p) {
    uint32_t a;
    asm("{ .reg .u64 t; cvta.to.shared.u64 t, %1; cvt.u32.u64 %0, t; }" : "=r"(a) : "l"(p));
    return a;
}

__device__ __forceinline__ void cp16(uint32_t saddr, const void* gptr) {
    asm volatile("cp.async.cg.shared.global [%0], [%1], 16;" :: "r"(saddr), "l"(gptr));
}
#define CP_COMMIT() asm volatile("cp.async.commit_group;" ::: "memory")
#define CP_WAIT(N)  asm volatile("cp.async.wait_group %0;" :: "n"(N) : "memory")

// ---------------------------------------------------------------------------
// Conversion kernels
// ---------------------------------------------------------------------------
__global__ __launch_bounds__(256) void convert_A_kernel(const float* __restrict__ A) {
    size_t i = ((size_t)blockIdx.x * blockDim.x + threadIdx.x) * 4;
    if (i >= (size_t)MROWS * EDIM) return;
    float4 v = *(const float4*)&A[i];
    __half h0, l0, h1, l1, h2, l2, h3, l3;
    split_half(v.x, h0, l0); split_half(v.y, h1, l1);
    split_half(v.z, h2, l2); split_half(v.w, h3, l3);
    __half2* ph = (__half2*)&g_Ahi[i];
    __half2* pl = (__half2*)&g_Alo[i];
    ph[0] = __half2(h0, h1); ph[1] = __half2(h2, h3);
    pl[0] = __half2(l0, l1); pl[1] = __half2(l2, l3);
}

__global__ __launch_bounds__(256) void convert_W_kernel(
    const float* __restrict__ Wq, const float* __restrict__ Wk,
    const float* __restrict__ Wv, const float* __restrict__ Wr) {
    int id = blockIdx.x * blockDim.x + threadIdx.x;   // n*256 + k
    if (id >= NCOLS * EDIM) return;
    int n = id >> 8;
    int k = id & 255;
    const float* W = (n < 256) ? Wq : (n < 512) ? Wk : (n < 768) ? Wv : Wr;
    g_Bh[(size_t)n * EDIM + k] = __float2half_rn(W[(size_t)k * EDIM + (n & 255)]);
}

// ---------------------------------------------------------------------------
// Projection GEMM via mma.sync + ldmatrix, cp.async 2-stage.
// Q,K (blockIdx.x < 4): split-fp16 2 products; V,R: single product.
// Epilogue: stage the 128x128 output tile in (now free) smem in record layout,
// then cooperative uint4 copy-out -> 64B-contiguous writes to g_att / g_R.
// ---------------------------------------------------------------------------
#define PSTR 72
#define PROJ_TILE (128 * PSTR * 2)           // 18432 B
#define PROJ_STAGE (3 * PROJ_TILE)           // 55296 B
#define PROJ_SMEM_BYTES (2 * PROJ_STAGE)     // 110592 B
#define ESTR 136                             // staging stride (halves / floats)

__global__ __launch_bounds__(256, 2) void proj_mma_kernel() {
    extern __shared__ __half smh[];
    const uint32_t sbase = smem_u32(smh);

    const int tid = threadIdx.x;
    const int wid = tid >> 5;
    const int lane = tid & 31;
    const int m0 = blockIdx.y * 128;
    const int n0 = blockIdx.x * 128;
    const bool twoProd = (blockIdx.x < 4);   // Q,K regions
    const int wm = (wid & 1) * 64;
    const int wn = (wid >> 1) * 32;
    const int grp = lane >> 2;
    const int tig = lane & 3;

    const int a_row = lane & 15;
    const int a_col = (lane >> 4) * 8;
    const int b_row = lane & 7;
    const int b_col = ((lane >> 3) & 1) * 8;
    const int b_nf  = lane >> 4;

    float acc[4][4][4];
#pragma unroll
    for (int mf = 0; mf < 4; mf++)
#pragma unroll
        for (int nf = 0; nf < 4; nf++)
#pragma unroll
            for (int r = 0; r < 4; r++) acc[mf][nf][r] = 0.f;

    auto fill = [&](int c, int st) {
        const int k0 = c * 64;
        const uint32_t sa = sbase + st * PROJ_STAGE;
#pragma unroll
        for (int it = 0; it < 4; it++) {
            int idx = tid + it * 256;          // 0..1023
            int r = idx >> 3;
            int c16 = idx & 7;
            uint32_t off = (uint32_t)(r * PSTR + c16 * 8) * 2;
            size_t ga = (size_t)(m0 + r) * EDIM + k0 + c16 * 8;
            size_t gb = (size_t)(n0 + r) * EDIM + k0 + c16 * 8;
            cp16(sa + off, g_Ahi + ga);
            if (twoProd) cp16(sa + PROJ_TILE + off, g_Alo + ga);
            cp16(sa + 2 * PROJ_TILE + off, g_Bh + gb);
        }
    };

    fill(0, 0); CP_COMMIT();
    fill(1, 1); CP_COMMIT();

    for (int c = 0; c < 4; c++) {
        if (c < 3) { CP_WAIT(1); } else { CP_WAIT(0); }
        __syncthreads();

        const int st = c & 1;
        const uint32_t sAh = sbase + st * PROJ_STAGE;
        const uint32_t sAl = sAh + PROJ_TILE;
        const uint32_t sB  = sAh + 2 * PROJ_TILE;

#pragma unroll
        for (int kk = 0; kk < 4; kk++) {
            const int kb0 = kk * 16;
            uint32_t b01[4], b23[4];
            ldsm_x4(b01, sB + (uint32_t)(((wn + b_nf * 8 + b_row) * PSTR) + kb0 + b_col) * 2);
            ldsm_x4(b23, sB + (uint32_t)(((wn + (2 + b_nf) * 8 + b_row) * PSTR) + kb0 + b_col) * 2);
#pragma unroll
            for (int mf = 0; mf < 4; mf++) {
                const uint32_t aoff = (uint32_t)(((wm + mf * 16 + a_row) * PSTR) + kb0 + a_col) * 2;
                uint32_t ah[4], al[4];
                ldsm_x4(ah, sAh + aoff);
                if (twoProd) ldsm_x4(al, sAl + aoff);
#pragma unroll
                for (int nf = 0; nf < 4; nf++) {
                    const uint32_t* bp = (nf < 2) ? (b01 + (nf & 1) * 2) : (b23 + (nf & 1) * 2);
                    mma16816(acc[mf][nf], ah, bp);
                    if (twoProd) mma16816(acc[mf][nf], al, bp);
                }
            }
        }
        __syncthreads();
        if (c + 2 < 4) { fill(c + 2, st); CP_COMMIT(); }
    }
    // All compute done and all warps past the final __syncthreads -> smem free.

    const int region = blockIdx.x >> 1;               // 0=Q 1=K 2=V 3=R
    const int nbase = (blockIdx.x & 1) * 128;
    const int head0 = (blockIdx.x & 1) * 4;

    if (region == 3) {
        // ---- stage fp32, copy contiguous rows to g_R ----
        float* sr = (float*)smh;
#pragma unroll
        for (int mf = 0; mf < 4; mf++) {
            int m = wm + mf * 16 + grp;
#pragma unroll
            for (int nf = 0; nf < 4; nf++) {
                int n = wn + nf * 8 + tig * 2;
                *(float2*)&sr[m * ESTR + n] = make_float2(acc[mf][nf][0], acc[mf][nf][1]);
                *(float2*)&sr[(m + 8) * ESTR + n] = make_float2(acc[mf][nf][2], acc[mf][nf][3]);
            }
        }
        __syncthreads();
#pragma unroll
        for (int s = 0; s < 16; s++) {
            int id = tid + s * 256;            // 0..4095
            int m = id >> 5;
            int ch = id & 31;                  // 16B chunk within 512B row
            *(uint4*)&g_R[(size_t)(m0 + m) * EDIM + nbase + ch * 4] =
                *(const uint4*)&sr[m * ESTR + ch * 4];
        }
    } else if (region == 0) {
        // ---- stage Q hi+lo, copy 64B segments into g_att ----
        __half* sh = smh;
        __half* sl = smh + 128 * ESTR;
#pragma unroll
        for (int mf = 0; mf < 4; mf++) {
            int m = wm + mf * 16 + grp;
#pragma unroll
            for (int nf = 0; nf < 4; nf++) {
                int n = wn + nf * 8 + tig * 2;
                __half h0, l0, h1, l1, h2, l2, h3, l3;
                split_half(acc[mf][nf][0], h0, l0); split_half(acc[mf][nf][1], h1, l1);
                split_half(acc[mf][nf][2], h2, l2); split_half(acc[mf][nf][3], h3, l3);
                *(__half2*)&sh[m * ESTR + n]       = __half2(h0, h1);
                *(__half2*)&sl[m * ESTR + n]       = __half2(l0, l1);
                *(__half2*)&sh[(m + 8) * ESTR + n] = __half2(h2, h3);
                *(__half2*)&sl[(m + 8) * ESTR + n] = __half2(l2, l3);
            }
        }
        __syncthreads();
#pragma unroll
        for (int s = 0; s < 8; s++) {
            int id = tid + s * 256;            // 0..2047
            int m = id >> 4;
            int r = id & 15;
            int head = r >> 2;
            int ch = r & 3;                    // 16B chunk within 64B segment
            size_t rec = ((size_t)(m0 + m) * HEADS + head0 + head) * 128;
            int so = m * ESTR + head * 32 + ch * 8;
            *(uint4*)&g_att[rec + ch * 8]      = *(const uint4*)&sh[so];
            *(uint4*)&g_att[rec + 32 + ch * 8] = *(const uint4*)&sl[so];
        }
    } else {
        // ---- stage K or V hi, copy 64B segments into g_att ----
        __half* sh = smh;
        const int seg = (region == 1) ? 64 : 96;
#pragma unroll
        for (int mf = 0; mf < 4; mf++) {
            int m = wm + mf * 16 + grp;
#pragma unroll
            for (int nf = 0; nf < 4; nf++) {
                int n = wn + nf * 8 + tig * 2;
                *(__half2*)&sh[m * ESTR + n] =
                    __floats2half2_rn(acc[mf][nf][0], acc[mf][nf][1]);
                *(__half2*)&sh[(m + 8) * ESTR + n] =
                    __floats2half2_rn(acc[mf][nf][2], acc[mf][nf][3]);
            }
        }
        __syncthreads();
#pragma unroll
        for (int s = 0; s < 8; s++) {
            int id = tid + s * 256;            // 0..2047
            int m = id >> 4;
            int r = id & 15;
            int head = r >> 2;
            int ch = r & 3;
            size_t rec = ((size_t)(m0 + m) * HEADS + head0 + head) * 128;
            *(uint4*)&g_att[rec + seg + ch * 8] =
                *(const uint4*)&sh[m * ESTR + head * 32 + ch * 8];
        }
    }
}

// ---------------------------------------------------------------------------
// Attention: packed fp16 records, cp.async loads, ldmatrix (+trans for V).
// S = (Qh+Ql) K^T (2 products); O = Ph V (single product; P in [0,1]).
// smem: 128 rows x 136 halves = 34816 B.
// ---------------------------------------------------------------------------
#define ASTR 136
#define ATT_SMEM_BYTES (128 * ASTR * 2)      // 34816

__global__ __launch_bounds__(256, 2) void attn_mma_kernel(float* __restrict__ out)
{
    extern __shared__ __half satt[];
    const uint32_t sb = smem_u32(satt);

    const int bh = blockIdx.x;
    const int b = bh >> 3;
    const int h = bh & 7;
    const int tid = threadIdx.x;
    const int wid = tid >> 5;
    const int lane = tid & 31;
    const int grp = lane >> 2;
    const int tig = lane & 3;

    const int a_row = lane & 15;
    const int a_col = (lane >> 4) * 8;
    const int b_row = lane & 7;
    const int b_col = ((lane >> 3) & 1) * 8;
    const int b_nf  = lane >> 4;
    const int t_k  = (lane & 7) + ((lane >> 3) & 1) * 8;
    const int t_n8 = (lane >> 4) * 8;

    // ---- async load of packed records ----
    const size_t gbase = ((size_t)(b * FDIM) * HEADS + h) * 128;
#pragma unroll
    for (int s = 0; s < 8; s++) {
        int idx = tid + s * 256;               // 0..2047
        int r = idx >> 4;
        int c16 = idx & 15;
        cp16(sb + (uint32_t)(r * ASTR + c16 * 8) * 2,
             g_att + gbase + (size_t)r * (HEADS * 128) + c16 * 8);
    }
    CP_COMMIT();
    CP_WAIT(0);
    __syncthreads();

    // ---- S = Q K^T : warp wid handles rows wm..wm+15, all 128 cols ----
    const int wm = wid * 16;
    float acc[16][4];
#pragma unroll
    for (int nf = 0; nf < 16; nf++)
#pragma unroll
        for (int r = 0; r < 4; r++) acc[nf][r] = 0.f;

#pragma unroll
    for (int kk = 0; kk < 2; kk++) {
        const int kb0 = kk * 16;
        const uint32_t aoff = (uint32_t)(((wm + a_row) * ASTR) + kb0 + a_col) * 2;
        uint32_t ah[4], al[4];
        ldsm_x4(ah, sb + aoff);                 // Qhi at seg 0
        ldsm_x4(al, sb + aoff + 64);            // Qlo at seg 32 (+64 B)
#pragma unroll
        for (int j = 0; j < 8; j++) {
            uint32_t bf[4];
            ldsm_x4(bf, sb + (uint32_t)((((2 * j + b_nf) * 8 + b_row) * ASTR) + 64 + kb0 + b_col) * 2);
            mma16816(acc[2 * j],     ah, bf);
            mma16816(acc[2 * j],     al, bf);
            mma16816(acc[2 * j + 1], ah, bf + 2);
            mma16816(acc[2 * j + 1], al, bf + 2);
        }
    }

    // ---- softmax in registers ----
    float mx0 = -1e30f, mx1 = -1e30f;
#pragma unroll
    for (int nf = 0; nf < 16; nf++) {
        mx0 = fmaxf(mx0, fmaxf(acc[nf][0], acc[nf][1]));
        mx1 = fmaxf(mx1, fmaxf(acc[nf][2], acc[nf][3]));
    }
#pragma unroll
    for (int o = 2; o >= 1; o >>= 1) {
        mx0 = fmaxf(mx0, __shfl_xor_sync(0xffffffffu, mx0, o));
        mx1 = fmaxf(mx1, __shfl_xor_sync(0xffffffffu, mx1, o));
    }
    float s0 = 0.f, s1 = 0.f;
#pragma unroll
    for (int nf = 0; nf < 16; nf++) {
        acc[nf][0] = __expf(acc[nf][0] - mx0);
        acc[nf][1] = __expf(acc[nf][1] - mx0);
        acc[nf][2] = __expf(acc[nf][2] - mx1);
        acc[nf][3] = __expf(acc[nf][3] - mx1);
        s0 += acc[nf][0] + acc[nf][1];
        s1 += acc[nf][2] + acc[nf][3];
    }
#pragma unroll
    for (int o = 2; o >= 1; o >>= 1) {
        s0 += __shfl_xor_sync(0xffffffffu, s0, o);
        s1 += __shfl_xor_sync(0xffffffffu, s1, o);
    }
    const float inv0 = 1.0f / s0;
    const float inv1 = 1.0f / s1;

    // ---- pack P (hi only) into A-fragments, consuming acc ----
    uint32_t ph[8][4];
#pragma unroll
    for (int j = 0; j < 8; j++) {
        ph[j][0] = pack2h(__float2half_rn(acc[2 * j][0] * inv0),
                          __float2half_rn(acc[2 * j][1] * inv0));
        ph[j][1] = pack2h(__float2half_rn(acc[2 * j][2] * inv1),
                          __float2half_rn(acc[2 * j][3] * inv1));
        ph[j][2] = pack2h(__float2half_rn(acc[2 * j + 1][0] * inv0),
                          __float2half_rn(acc[2 * j + 1][1] * inv0));
        ph[j][3] = pack2h(__float2half_rn(acc[2 * j + 1][2] * inv1),
                          __float2half_rn(acc[2 * j + 1][3] * inv1));
    }

    // ---- O = P V : V row-major in record (seg 96), B-frags via ldmatrix.trans ----
    float o[4][4];
#pragma unroll
    for (int nf = 0; nf < 4; nf++)
#pragma unroll
        for (int r = 0; r < 4; r++) o[nf][r] = 0.f;

#pragma unroll
    for (int kk = 0; kk < 8; kk++) {
        const int kb0 = kk * 16;
        uint32_t b01[4], b23[4];
        ldsm_x4_trans(b01, sb + (uint32_t)(((kb0 + t_k) * ASTR) + 96 + 0  + t_n8) * 2);
        ldsm_x4_trans(b23, sb + (uint32_t)(((kb0 + t_k) * ASTR) + 96 + 16 + t_n8) * 2);
#pragma unroll
        for (int nf = 0; nf < 4; nf++) {
            const uint32_t* bp = (nf < 2) ? (b01 + (nf & 1) * 2) : (b23 + (nf & 1) * 2);
            mma16816(o[nf], ph[kk], bp);
        }
    }

    // ---- epilogue: + residual, ReLU, store ----
    const size_t orowbase = (size_t)(b * FDIM);
    const int colQ = h * DHEAD;
#pragma unroll
    for (int nf = 0; nf < 4; nf++) {
        int cc = nf * 8 + tig * 2;
        int r0 = wm + grp;
        int r1 = r0 + 8;
        float2 rr0 = *(const float2*)&g_R[(orowbase + r0) * EDIM + colQ + cc];
        float2 rr1 = *(const float2*)&g_R[(orowbase + r1) * EDIM + colQ + cc];
        float2 o0, o1;
        o0.x = fmaxf(o[nf][0] + rr0.x, 0.f);
        o0.y = fmaxf(o[nf][1] + rr0.y, 0.f);
        o1.x = fmaxf(o[nf][2] + rr1.x, 0.f);
        o1.y = fmaxf(o[nf][3] + rr1.y, 0.f);
        *(float2*)&out[(orowbase + r0) * EDIM + colQ + cc] = o0;
        *(float2*)&out[(orowbase + r1) * EDIM + colQ + cc] = o1;
    }
}

// ---------------------------------------------------------------------------
// Launch
// ---------------------------------------------------------------------------
extern "C" void kernel_launch(void* const* d_in, const int* in_sizes, int n_in,
                              void* d_out, int out_size)
{
    const float* inputs = (const float*)d_in[0];
    const float* Wq     = (const float*)d_in[1];
    const float* Wk     = (const float*)d_in[2];
    const float* Wv     = (const float*)d_in[3];
    const float* Wr     = (const float*)d_in[4];
    float* out = (float*)d_out;

    cudaFuncSetAttribute(proj_mma_kernel, cudaFuncAttributeMaxDynamicSharedMemorySize,
                         PROJ_SMEM_BYTES);
    cudaFuncSetAttribute(attn_mma_kernel, cudaFuncAttributeMaxDynamicSharedMemorySize,
                         ATT_SMEM_BYTES);

    convert_A_kernel<<<(MROWS * EDIM / 4 + 255) / 256, 256>>>(inputs);
    convert_W_kernel<<<(NCOLS * EDIM + 255) / 256, 256>>>(Wq, Wk, Wv, Wr);

    dim3 gridP(NCOLS / 128, MROWS / 128);   // 8 x 1024
    proj_mma_kernel<<<gridP, 256, PROJ_SMEM_BYTES>>>();

    attn_mma_kernel<<<BATCH * HEADS, 256, ATT_SMEM_BYTES>>>(out);
}